// round 13
// baseline (speedup 1.0000x reference)
#include <cuda_runtime.h>
#include <cuda_fp16.h>
#include <cstdint>

// ---------------- problem dims ----------------
#define TT 2048
#define BB 16
#define DDIM 1024
#define MM (TT*BB)            // 32768 rows
#define SBD (BB*DDIM)         // 16384 lanes in scan
#define NELEM ((size_t)MM*DDIM)

// ---------------- device scratch (no cudaMalloc allowed) ----------------
__device__ __half g_xh[NELEM];
__device__ __half g_wh[2*DDIM*DDIM];
__device__ float g_alpha[NELEM];
__device__ float g_vraw[NELEM];

// ---------------- PTX helpers (base sm_103 target: no tcgen05/TMA) ---------
__device__ __forceinline__ uint32_t smem_u32(const void* p) {
    uint32_t a;
    asm("{ .reg .u64 t; cvta.to.shared.u64 t, %1; cvt.u32.u64 %0, t; }" : "=r"(a) : "l"(p));
    return a;
}
__device__ __forceinline__ void cp16(uint32_t s, const void* g) {
    asm volatile("cp.async.cg.shared.global [%0], [%1], 16;" :: "r"(s), "l"(g));
}
__device__ __forceinline__ void cp_commit() {
    asm volatile("cp.async.commit_group;" ::: "memory");
}
template <int N>
__device__ __forceinline__ void cp_wait() {
    asm volatile("cp.async.wait_group %0;" :: "n"(N) : "memory");
}
__device__ __forceinline__ void ldsm4(uint32_t* r, uint32_t addr) {
    asm volatile("ldmatrix.sync.aligned.m8n8.x4.shared.b16 {%0,%1,%2,%3}, [%4];"
                 : "=r"(r[0]), "=r"(r[1]), "=r"(r[2]), "=r"(r[3]) : "r"(addr));
}
__device__ __forceinline__ void hmma(float* c, const uint32_t* a, uint32_t b0, uint32_t b1) {
    asm volatile("mma.sync.aligned.m16n8k16.row.col.f32.f16.f16.f32 "
                 "{%0,%1,%2,%3}, {%4,%5,%6,%7}, {%8,%9}, {%0,%1,%2,%3};"
                 : "+f"(c[0]), "+f"(c[1]), "+f"(c[2]), "+f"(c[3])
                 : "r"(a[0]), "r"(a[1]), "r"(a[2]), "r"(a[3]), "r"(b0), "r"(b1));
}

// fast tanh via exp2-based __expf; |v| < ~44 avoids overflow (z range << 44)
__device__ __forceinline__ float fast_tanh(float v) {
    float vc = fminf(fmaxf(v, -15.0f), 15.0f);
    float t = __expf(2.0f * vc);
    return __fdividef(t - 1.0f, t + 1.0f);
}

// ---------------- quantization kernels (fp32 -> fp16) ----------------
__global__ void quant_x_kernel(const float* __restrict__ x) {
    size_t i = (size_t)blockIdx.x * blockDim.x + threadIdx.x;  // float4 index
    if (i >= NELEM / 4) return;
    float4 v = reinterpret_cast<const float4*>(x)[i];
    float f[4] = {v.x, v.y, v.z, v.w};
    union { __half h[4]; uint2 u; } H;
#pragma unroll
    for (int j = 0; j < 4; j++) H.h[j] = __float2half_rn(f[j]);
    reinterpret_cast<uint2*>(g_xh)[i] = H.u;
}

__global__ void quant_w_kernel(const float* __restrict__ Wa, const float* __restrict__ Wx) {
    size_t i = (size_t)blockIdx.x * blockDim.x + threadIdx.x;  // float4 idx over 2 mats
    const size_t nper = (size_t)DDIM * DDIM / 4;
    if (i >= 2 * nper) return;
    const float* src = (i < nper) ? Wa : Wx;
    size_t j = (i < nper) ? i : i - nper;
    float4 v = reinterpret_cast<const float4*>(src)[j];
    float f[4] = {v.x, v.y, v.z, v.w};
    union { __half h[4]; uint2 u; } H;
#pragma unroll
    for (int k = 0; k < 4; k++) H.h[k] = __float2half_rn(f[k]);
    reinterpret_cast<uint2*>(g_wh)[i] = H.u;
}

// ---------------- GEMM: out[m,e] = act( sum_d x[m,d]*W[e,d] + bias[e] ) ------
// plain fp16, fp32 accumulate. CTA 128x128x64, 128 thr (4 warps, warp tile
// 64x64 — halves smem read redundancy), 3-stage cp.async ring, 2 CTAs/SM.
static constexpr int BK   = 64;              // k elems per chunk (128B of fp16)
static constexpr int ROWB = 144;             // 128B data + 16B pad
static constexpr int XH_TILE_B = 128 * ROWB; // 18432
static constexpr int WH_TILE_B = 128 * ROWB; // 18432
static constexpr int ST_XH = 0;
static constexpr int ST_WH = ST_XH + XH_TILE_B;
static constexpr int STAGE_B = ST_WH + WH_TILE_B;   // 36864
static constexpr int NSTAGE  = 3;
static constexpr int SMEM_GEMM_TOTAL = NSTAGE * STAGE_B;  // 110592 (x2 CTAs = 221184)
static constexpr int NKC = DDIM / BK;        // 16

__global__ void __launch_bounds__(128, 2)
gemm_kernel(const float* __restrict__ b_alpha, const float* __restrict__ b_v) {
    extern __shared__ char smem[];
    const uint32_t sbase = smem_u32(smem);
    const int tid = threadIdx.x;
    const int wid = tid >> 5;
    const int l   = tid & 31;
    const int wid_m = wid >> 1;      // 0..1  (64-row slabs)
    const int wid_n = wid & 1;       // 0..1  (64-col slabs)
    const int bn = blockIdx.x;       // 0..7   (N tiles of 128)
    const int bm = blockIdx.y;       // 0..255 (M tiles of 128)
    const int ws = blockIdx.z;       // 0: alpha/sigmoid, 1: vraw/tanh

    const __half* __restrict__ Xg  = g_xh + (size_t)bm * 128 * DDIM;
    const __half* __restrict__ Whg = g_wh + (size_t)ws * DDIM * DDIM + (size_t)bn * 128 * DDIM;
    float* __restrict__ outp = ws ? g_vraw : g_alpha;
    const float* __restrict__ bias = ws ? b_v : b_alpha;

    // cp.async mapping: 128 threads; X,W tiles each 128 rows x 128B.
    // Thread t owns full row t of both tiles: 8 cp16 for X + 8 cp16 for W.
    auto issue_stage = [&](int stage, int kc) {
        const uint32_t s0 = sbase + stage * STAGE_B;
        const size_t gof = (size_t)kc * BK;               // halves
        const uint32_t so = tid * ROWB;
#pragma unroll
        for (int j = 0; j < 8; j++)
            cp16(s0 + ST_XH + so + j * 16, Xg + (size_t)tid * DDIM + gof + j * 8);
#pragma unroll
        for (int j = 0; j < 8; j++)
            cp16(s0 + ST_WH + so + j * 16, Whg + (size_t)tid * DDIM + gof + j * 8);
        cp_commit();
    };

    // ldmatrix lane offsets (ROWB=144: 16 rows mod 128 distinct -> conflict-free)
    // B map: n-slice q within an x4 load uses regs {r[2q], r[2q+1]}
    const uint32_t a_lane_off = (uint32_t)((l & 15) * ROWB + (l >> 4) * 16);
    const uint32_t b_lane_off = (uint32_t)(((l & 7) + ((l >> 4) << 3)) * ROWB + ((l >> 3) & 1) * 16);

    float acc[4][8][4];
#pragma unroll
    for (int mi = 0; mi < 4; mi++)
#pragma unroll
        for (int ni = 0; ni < 8; ni++)
#pragma unroll
            for (int r = 0; r < 4; r++) acc[mi][ni][r] = 0.0f;

    issue_stage(0, 0);
    issue_stage(1, 1);

    int rd = 0, wr = 2;
#pragma unroll 1
    for (int kc = 0; kc < NKC; kc++) {
        if (kc + 1 < NKC) cp_wait<1>(); else cp_wait<0>();
        __syncthreads();
        if (kc + 2 < NKC) issue_stage(wr, kc + 2);

        const uint32_t s0 = sbase + rd * STAGE_B;
        const uint32_t sXH = s0 + ST_XH + (uint32_t)(wid_m * 64 * ROWB) + a_lane_off;
        const uint32_t sWH = s0 + ST_WH + (uint32_t)(wid_n * 64 * ROWB) + b_lane_off;

#pragma unroll
        for (int ks = 0; ks < 4; ks++) {
            uint32_t ah[4][4];
#pragma unroll
            for (int mi = 0; mi < 4; mi++)
                ldsm4(ah[mi], sXH + mi * 16 * ROWB + ks * 32);
#pragma unroll
            for (int p = 0; p < 4; p++) {
                uint32_t bh[4];
                ldsm4(bh, sWH + p * 16 * ROWB + ks * 32);
#pragma unroll
                for (int mi = 0; mi < 4; mi++) {
                    hmma(acc[mi][2*p+0], ah[mi], bh[0], bh[1]);
                    hmma(acc[mi][2*p+1], ah[mi], bh[2], bh[3]);
                }
            }
        }
        rd = (rd + 1 == NSTAGE) ? 0 : rd + 1;
        wr = (wr + 1 == NSTAGE) ? 0 : wr + 1;
    }

    // epilogue: z = acc + bias; activation; float2 stores
    const int row_base = bm * 128 + wid_m * 64 + (l >> 2);
    const int col_base = bn * 128 + wid_n * 64 + (l & 3) * 2;
#pragma unroll
    for (int mi = 0; mi < 4; mi++) {
#pragma unroll
        for (int n8 = 0; n8 < 8; n8++) {
            const int col = col_base + n8 * 8;
            const float bia0 = __ldg(&bias[col]);
            const float bia1 = __ldg(&bias[col + 1]);
#pragma unroll
            for (int half = 0; half < 2; half++) {
                const int row = row_base + mi * 16 + half * 8;
                float v0 = acc[mi][n8][half*2+0] + bia0;
                float v1 = acc[mi][n8][half*2+1] + bia1;
                float2 o;
                if (ws) { o.x = fast_tanh(v0); o.y = fast_tanh(v1); }
                else {
                    o.x = __fdividef(1.0f, 1.0f + __expf(-v0));
                    o.y = __fdividef(1.0f, 1.0f + __expf(-v1));
                }
                *reinterpret_cast<float2*>(outp + (size_t)row * DDIM + col) = o;
            }
        }
    }
}

// ---------------- scan kernel: 16384 independent recurrences over T ----------
// 32-thread blocks; 4-slot cp.async smem ring, 8 steps/chunk, 2-chunk lead.
__global__ void __launch_bounds__(32)
scan_kernel(const float* __restrict__ d_g, const float* __restrict__ b_g,
            float* __restrict__ out) {
    __shared__ __align__(16) float sA[4][8][32];
    __shared__ __align__(16) float sV[4][8][32];
    const int lane = threadIdx.x;
    const int base = blockIdx.x * 32;
    const int idx = base + lane;
    const int d = idx & (DDIM - 1);
    const float LOG2E = 1.4426950408889634f;
    const float dgl = __ldg(&d_g[d]) * LOG2E;
    const float bgl = __ldg(&b_g[d]) * LOG2E;

    float* houtp = out + (size_t)TT * SBD;   // h buffer [T+1, B, D]
    houtp[idx] = 0.0f;                       // h0

    const float* A = g_alpha;
    const float* V = g_vraw;

    const int seg = lane & 7;        // 16B segment within a 128B row
    const int r0  = lane >> 3;       // 0..3

    auto issue_chunk = [&](int c) {
        const int slot = c & 3;
#pragma unroll
        for (int rr = 0; rr < 4; rr++) {
            const int r = r0 + rr * 4;             // 0..15
            const int step = r & 7;
            const size_t gidx = (size_t)(c * 8 + step) * SBD + base + seg * 4;
            const float* src = (r < 8) ? (A + gidx) : (V + gidx);
            float* dst = (r < 8) ? &sA[slot][step][seg * 4] : &sV[slot][step][seg * 4];
            cp16(smem_u32(dst), src);
        }
        cp_commit();
    };

    issue_chunk(0);
    issue_chunk(1);
    issue_chunk(2);

    float h = 0.0f;
#pragma unroll 1
    for (int t0 = 0; t0 < TT; t0 += 8) {
        __syncwarp();
        if (t0 + 24 < TT)       { issue_chunk((t0 >> 3) + 3); cp_wait<3>(); }
        else if (t0 + 24 == TT) cp_wait<2>();
        else if (t0 + 16 == TT) cp_wait<1>();
        else                    cp_wait<0>();
        __syncwarp();

        const int slot = (t0 >> 3) & 3;
#pragma unroll
        for (int i = 0; i < 8; i++) {
            const float a  = sA[slot][i][lane];
            const float cv = sV[slot][i][lane];
            const float c  = (1.0f - a) * cv;      // off critical chain
            const float ah = a * h;                // parallel with g-chain
            const float ex = exp2f(fmaf(dgl, fabsf(h), -bgl));
            const float g = __fdividef(1.0f, 1.0f + ex);
            h = fmaf(c, g, ah);                    // h_new
            const float sg = __fdividef(1.0f, 1.0f + exp2f(-h * LOG2E));
            const size_t t = (size_t)(t0 + i);
            out[t * SBD + idx] = h * h * sg;       // h * silu(h)
            houtp[(t + 1) * SBD + idx] = h;
        }
    }
}

// ---------------- launcher ----------------
extern "C" void kernel_launch(void* const* d_in, const int* in_sizes, int n_in,
                              void* d_out, int out_size) {
    const float* x       = (const float*)d_in[0];
    const float* W_alpha = (const float*)d_in[1];
    const float* b_alpha = (const float*)d_in[2];
    const float* d_g     = (const float*)d_in[3];
    const float* b_g     = (const float*)d_in[4];
    const float* W_x     = (const float*)d_in[5];
    const float* b_v     = (const float*)d_in[6];
    float* out = (float*)d_out;

    (void)in_sizes; (void)n_in; (void)out_size;

    cudaFuncSetAttribute(gemm_kernel, cudaFuncAttributeMaxDynamicSharedMemorySize,
                         SMEM_GEMM_TOTAL);

    // 1) quantize fp32 -> fp16
    {
        const int n4 = (int)(NELEM / 4);
        quant_x_kernel<<<(n4 + 255) / 256, 256>>>(x);
        const int w4 = 2 * DDIM * DDIM / 4;
        quant_w_kernel<<<(w4 + 255) / 256, 256>>>(W_alpha, W_x);
    }

    // 2) single fused GEMM launch (z=0: alpha/sigmoid, z=1: vraw/tanh)
    {
        dim3 grid(DDIM / 128, MM / 128, 2);
        gemm_kernel<<<grid, 128, SMEM_GEMM_TOTAL>>>(b_alpha, b_v);
    }

    // 3) sequential scan, fully parallel over B*D lanes
    scan_kernel<<<SBD / 32, 32>>>(d_g, b_g, out);
}

// round 14
// speedup vs baseline: 1.2113x; 1.2113x over previous
#include <cuda_runtime.h>
#include <cuda_fp16.h>
#include <cstdint>

// ---------------- problem dims ----------------
#define TT 2048
#define BB 16
#define DDIM 1024
#define MM (TT*BB)            // 32768 rows
#define SBD (BB*DDIM)         // 16384 lanes in scan
#define NELEM ((size_t)MM*DDIM)

// ---------------- device scratch (no cudaMalloc allowed) ----------------
__device__ __half g_xh[NELEM];
__device__ __half g_wh[2*DDIM*DDIM];
__device__ float g_alpha[NELEM];
__device__ float g_vraw[NELEM];

// ---------------- PTX helpers (base sm_103 target: no tcgen05/TMA) ---------
__device__ __forceinline__ uint32_t smem_u32(const void* p) {
    uint32_t a;
    asm("{ .reg .u64 t; cvta.to.shared.u64 t, %1; cvt.u32.u64 %0, t; }" : "=r"(a) : "l"(p));
    return a;
}
__device__ __forceinline__ void cp16(uint32_t s, const void* g) {
    asm volatile("cp.async.cg.shared.global [%0], [%1], 16;" :: "r"(s), "l"(g));
}
__device__ __forceinline__ void cp_commit() {
    asm volatile("cp.async.commit_group;" ::: "memory");
}
template <int N>
__device__ __forceinline__ void cp_wait() {
    asm volatile("cp.async.wait_group %0;" :: "n"(N) : "memory");
}
__device__ __forceinline__ void ldsm4(uint32_t* r, uint32_t addr) {
    asm volatile("ldmatrix.sync.aligned.m8n8.x4.shared.b16 {%0,%1,%2,%3}, [%4];"
                 : "=r"(r[0]), "=r"(r[1]), "=r"(r[2]), "=r"(r[3]) : "r"(addr));
}
__device__ __forceinline__ void hmma(float* c, const uint32_t* a, uint32_t b0, uint32_t b1) {
    asm volatile("mma.sync.aligned.m16n8k16.row.col.f32.f16.f16.f32 "
                 "{%0,%1,%2,%3}, {%4,%5,%6,%7}, {%8,%9}, {%0,%1,%2,%3};"
                 : "+f"(c[0]), "+f"(c[1]), "+f"(c[2]), "+f"(c[3])
                 : "r"(a[0]), "r"(a[1]), "r"(a[2]), "r"(a[3]), "r"(b0), "r"(b1));
}
__device__ __forceinline__ float tanh_approx(float x) {
    float t;
    asm("tanh.approx.f32 %0, %1;" : "=f"(t) : "f"(x));
    return t;
}
// fast tanh via __expf; |v| clamped (z range << 15)
__device__ __forceinline__ float fast_tanh(float v) {
    float vc = fminf(fmaxf(v, -15.0f), 15.0f);
    float t = __expf(2.0f * vc);
    return __fdividef(t - 1.0f, t + 1.0f);
}

// ---------------- quantization kernels (fp32 -> fp16) ----------------
__global__ void quant_x_kernel(const float* __restrict__ x) {
    size_t i = (size_t)blockIdx.x * blockDim.x + threadIdx.x;  // float4 index
    if (i >= NELEM / 4) return;
    float4 v = reinterpret_cast<const float4*>(x)[i];
    float f[4] = {v.x, v.y, v.z, v.w};
    union { __half h[4]; uint2 u; } H;
#pragma unroll
    for (int j = 0; j < 4; j++) H.h[j] = __float2half_rn(f[j]);
    reinterpret_cast<uint2*>(g_xh)[i] = H.u;
}

__global__ void quant_w_kernel(const float* __restrict__ Wa, const float* __restrict__ Wx) {
    size_t i = (size_t)blockIdx.x * blockDim.x + threadIdx.x;  // float4 idx over 2 mats
    const size_t nper = (size_t)DDIM * DDIM / 4;
    if (i >= 2 * nper) return;
    const float* src = (i < nper) ? Wa : Wx;
    size_t j = (i < nper) ? i : i - nper;
    float4 v = reinterpret_cast<const float4*>(src)[j];
    float f[4] = {v.x, v.y, v.z, v.w};
    union { __half h[4]; uint2 u; } H;
#pragma unroll
    for (int k = 0; k < 4; k++) H.h[k] = __float2half_rn(f[k]);
    reinterpret_cast<uint2*>(g_wh)[i] = H.u;
}

// ---------------- GEMM: out[m,e] = act( sum_d x[m,d]*W[e,d] + bias[e] ) ------
// plain fp16, fp32 accumulate. CTA 128x128x64, 256 thr (8 warps, warp tile
// 32x64), 3-stage cp.async ring, TWO CTAs per SM (R12 config — measured best).
static constexpr int BK   = 64;              // k elems per chunk (128B of fp16)
static constexpr int ROWB = 144;             // 128B data + 16B pad
static constexpr int XH_TILE_B = 128 * ROWB; // 18432
static constexpr int WH_TILE_B = 128 * ROWB; // 18432
static constexpr int ST_XH = 0;
static constexpr int ST_WH = ST_XH + XH_TILE_B;
static constexpr int STAGE_B = ST_WH + WH_TILE_B;   // 36864
static constexpr int NSTAGE  = 3;
static constexpr int SMEM_GEMM_TOTAL = NSTAGE * STAGE_B;  // 110592 (x2 CTAs = 221184)
static constexpr int NKC = DDIM / BK;        // 16

__global__ void __launch_bounds__(256, 2)
gemm_kernel(const float* __restrict__ b_alpha, const float* __restrict__ b_v) {
    extern __shared__ char smem[];
    const uint32_t sbase = smem_u32(smem);
    const int tid = threadIdx.x;
    const int wid = tid >> 5;
    const int l   = tid & 31;
    const int wid_m = wid >> 1;      // 0..3  (32-row slabs)
    const int wid_n = wid & 1;       // 0..1  (64-col slabs)
    const int bn = blockIdx.x;       // 0..7   (N tiles of 128)
    const int bm = blockIdx.y;       // 0..255 (M tiles of 128)
    const int ws = blockIdx.z;       // 0: alpha/sigmoid, 1: vraw/tanh

    const __half* __restrict__ Xg  = g_xh + (size_t)bm * 128 * DDIM;
    const __half* __restrict__ Whg = g_wh + (size_t)ws * DDIM * DDIM + (size_t)bn * 128 * DDIM;
    float* __restrict__ outp = ws ? g_vraw : g_alpha;
    const float* __restrict__ bias = ws ? b_v : b_alpha;

    // cp.async mapping: 256 threads; X,W tiles each 128 rows x 128B.
    // Each thread: one 64B half-row of X and of W (4 cp16 each).
    const int crow  = tid >> 1;      // 0..127
    const int chalf = tid & 1;       // which 64B half of the 128B k-slice
    auto issue_stage = [&](int stage, int kc) {
        const uint32_t s0 = sbase + stage * STAGE_B;
        const size_t gof = (size_t)kc * BK + chalf * 32;  // halves
        const uint32_t so = crow * ROWB + chalf * 64;
#pragma unroll
        for (int j = 0; j < 4; j++)
            cp16(s0 + ST_XH + so + j * 16, Xg + (size_t)crow * DDIM + gof + j * 8);
#pragma unroll
        for (int j = 0; j < 4; j++)
            cp16(s0 + ST_WH + so + j * 16, Whg + (size_t)crow * DDIM + gof + j * 8);
        cp_commit();
    };

    // ldmatrix lane offsets (ROWB=144: 16 rows mod 128 distinct -> conflict-free)
    // B map: n-slice q within an x4 load uses regs {r[2q], r[2q+1]}
    const uint32_t a_lane_off = (uint32_t)((l & 15) * ROWB + (l >> 4) * 16);
    const uint32_t b_lane_off = (uint32_t)(((l & 7) + ((l >> 4) << 3)) * ROWB + ((l >> 3) & 1) * 16);

    float acc[2][8][4];
#pragma unroll
    for (int mi = 0; mi < 2; mi++)
#pragma unroll
        for (int ni = 0; ni < 8; ni++)
#pragma unroll
            for (int r = 0; r < 4; r++) acc[mi][ni][r] = 0.0f;

    issue_stage(0, 0);
    issue_stage(1, 1);

    int rd = 0, wr = 2;
#pragma unroll 1
    for (int kc = 0; kc < NKC; kc++) {
        if (kc + 1 < NKC) cp_wait<1>(); else cp_wait<0>();
        __syncthreads();
        if (kc + 2 < NKC) issue_stage(wr, kc + 2);

        const uint32_t s0 = sbase + rd * STAGE_B;
        const uint32_t sXH = s0 + ST_XH + (uint32_t)(wid_m * 32 * ROWB) + a_lane_off;
        const uint32_t sWH = s0 + ST_WH + (uint32_t)(wid_n * 64 * ROWB) + b_lane_off;

#pragma unroll
        for (int ks = 0; ks < 4; ks++) {
            uint32_t ah[2][4];
            ldsm4(ah[0], sXH + ks * 32);
            ldsm4(ah[1], sXH + 16 * ROWB + ks * 32);
#pragma unroll
            for (int p = 0; p < 4; p++) {
                uint32_t bh[4];
                ldsm4(bh, sWH + p * 16 * ROWB + ks * 32);
#pragma unroll
                for (int mi = 0; mi < 2; mi++) {
                    hmma(acc[mi][2*p+0], ah[mi], bh[0], bh[1]);
                    hmma(acc[mi][2*p+1], ah[mi], bh[2], bh[3]);
                }
            }
        }
        rd = (rd + 1 == NSTAGE) ? 0 : rd + 1;
        wr = (wr + 1 == NSTAGE) ? 0 : wr + 1;
    }

    // epilogue: z = acc + bias; activation; float2 stores
    const int row_base = bm * 128 + wid_m * 32 + (l >> 2);
    const int col_base = bn * 128 + wid_n * 64 + (l & 3) * 2;
#pragma unroll
    for (int mi = 0; mi < 2; mi++) {
#pragma unroll
        for (int n8 = 0; n8 < 8; n8++) {
            const int col = col_base + n8 * 8;
            const float bia0 = __ldg(&bias[col]);
            const float bia1 = __ldg(&bias[col + 1]);
#pragma unroll
            for (int half = 0; half < 2; half++) {
                const int row = row_base + mi * 16 + half * 8;
                float v0 = acc[mi][n8][half*2+0] + bia0;
                float v1 = acc[mi][n8][half*2+1] + bia1;
                float2 o;
                if (ws) { o.x = fast_tanh(v0); o.y = fast_tanh(v1); }
                else {
                    o.x = __fdividef(1.0f, 1.0f + __expf(-v0));
                    o.y = __fdividef(1.0f, 1.0f + __expf(-v1));
                }
                *reinterpret_cast<float2*>(outp + (size_t)row * DDIM + col) = o;
            }
        }
    }
}

// ---------------- scan kernel: 16384 independent recurrences over T ----------
// 32-thread blocks; 4-slot cp.async smem ring, 8 steps/chunk, 2-chunk lead.
// In-chain gate via MUFU.TANH: g = 0.5 + 0.5*tanh((b - d|h|)/2); chain
// fabs->fma->tanh->fma = ~28 cyc. Off-chain silu keeps exact __expf sigmoid.
__global__ void __launch_bounds__(32)
scan_kernel(const float* __restrict__ d_g, const float* __restrict__ b_g,
            float* __restrict__ out) {
    __shared__ __align__(16) float sA[4][8][32];
    __shared__ __align__(16) float sV[4][8][32];
    const int lane = threadIdx.x;
    const int base = blockIdx.x * 32;
    const int idx = base + lane;
    const int d = idx & (DDIM - 1);
    const float dq = -0.5f * __ldg(&d_g[d]);   // tanh arg: dq*|h| + bq
    const float bq =  0.5f * __ldg(&b_g[d]);

    float* houtp = out + (size_t)TT * SBD;   // h buffer [T+1, B, D]
    houtp[idx] = 0.0f;                       // h0

    const float* A = g_alpha;
    const float* V = g_vraw;

    const int seg = lane & 7;        // 16B segment within a 128B row
    const int r0  = lane >> 3;       // 0..3

    auto issue_chunk = [&](int c) {
        const int slot = c & 3;
#pragma unroll
        for (int rr = 0; rr < 4; rr++) {
            const int r = r0 + rr * 4;             // 0..15
            const int step = r & 7;
            const size_t gidx = (size_t)(c * 8 + step) * SBD + base + seg * 4;
            const float* src = (r < 8) ? (A + gidx) : (V + gidx);
            float* dst = (r < 8) ? &sA[slot][step][seg * 4] : &sV[slot][step][seg * 4];
            cp16(smem_u32(dst), src);
        }
        cp_commit();
    };

    issue_chunk(0);
    issue_chunk(1);
    issue_chunk(2);

    float h = 0.0f;
#pragma unroll 1
    for (int t0 = 0; t0 < TT; t0 += 8) {
        __syncwarp();
        if (t0 + 24 < TT)       { issue_chunk((t0 >> 3) + 3); cp_wait<3>(); }
        else if (t0 + 24 == TT) cp_wait<2>();
        else if (t0 + 16 == TT) cp_wait<1>();
        else                    cp_wait<0>();
        __syncwarp();

        const int slot = (t0 >> 3) & 3;
#pragma unroll
        for (int i = 0; i < 8; i++) {
            const float a  = sA[slot][i][lane];
            const float cv = sV[slot][i][lane];
            const float halfc = 0.5f * (1.0f - a) * cv;   // off chain
            const float base_h = fmaf(a, h, halfc);       // parallel w/ fabs path
            const float u = fmaf(dq, fabsf(h), bq);       // chain: fabs->fma
            const float t = tanh_approx(u);               // chain: MUFU.TANH
            h = fmaf(halfc, t, base_h);                   // chain: fma -> h_new
            const float sg = __fdividef(1.0f, 1.0f + __expf(-h));  // off chain
            const size_t tt = (size_t)(t0 + i);
            out[tt * SBD + idx] = h * h * sg;             // h * silu(h)
            houtp[(tt + 1) * SBD + idx] = h;
        }
    }
}

// ---------------- launcher ----------------
extern "C" void kernel_launch(void* const* d_in, const int* in_sizes, int n_in,
                              void* d_out, int out_size) {
    const float* x       = (const float*)d_in[0];
    const float* W_alpha = (const float*)d_in[1];
    const float* b_alpha = (const float*)d_in[2];
    const float* d_g     = (const float*)d_in[3];
    const float* b_g     = (const float*)d_in[4];
    const float* W_x     = (const float*)d_in[5];
    const float* b_v     = (const float*)d_in[6];
    float* out = (float*)d_out;

    (void)in_sizes; (void)n_in; (void)out_size;

    cudaFuncSetAttribute(gemm_kernel, cudaFuncAttributeMaxDynamicSharedMemorySize,
                         SMEM_GEMM_TOTAL);

    // 1) quantize fp32 -> fp16
    {
        const int n4 = (int)(NELEM / 4);
        quant_x_kernel<<<(n4 + 255) / 256, 256>>>(x);
        const int w4 = 2 * DDIM * DDIM / 4;
        quant_w_kernel<<<(w4 + 255) / 256, 256>>>(W_alpha, W_x);
    }

    // 2) single fused GEMM launch (z=0: alpha/sigmoid, z=1: vraw/tanh)
    {
        dim3 grid(DDIM / 128, MM / 128, 2);
        gemm_kernel<<<grid, 256, SMEM_GEMM_TOTAL>>>(b_alpha, b_v);
    }

    // 3) sequential scan, fully parallel over B*D lanes
    scan_kernel<<<SBD / 32, 32>>>(d_g, b_g, out);
}

// round 16
// speedup vs baseline: 1.2460x; 1.0287x over previous
#include <cuda_runtime.h>
#include <cuda_fp16.h>
#include <cstdint>

// ---------------- problem dims ----------------
#define TT 2048
#define BB 16
#define DDIM 1024
#define MM (TT*BB)            // 32768 rows
#define SBD (BB*DDIM)         // 16384 lanes in scan
#define NELEM ((size_t)MM*DDIM)

// ---------------- device scratch (no cudaMalloc allowed) ----------------
__device__ __half g_xh[NELEM];
__device__ __half g_wh[2*DDIM*DDIM];
__device__ __half g_am[NELEM];    // 1 - alpha  (fp16, inverted storage)
__device__ __half g_v[NELEM];     // tanh(zv)   (fp16)

// ---------------- PTX helpers (base sm_103 target: no tcgen05/TMA) ---------
__device__ __forceinline__ uint32_t smem_u32(const void* p) {
    uint32_t a;
    asm("{ .reg .u64 t; cvta.to.shared.u64 t, %1; cvt.u32.u64 %0, t; }" : "=r"(a) : "l"(p));
    return a;
}
__device__ __forceinline__ void cp16(uint32_t s, const void* g) {
    asm volatile("cp.async.cg.shared.global [%0], [%1], 16;" :: "r"(s), "l"(g));
}
__device__ __forceinline__ void cp_commit() {
    asm volatile("cp.async.commit_group;" ::: "memory");
}
template <int N>
__device__ __forceinline__ void cp_wait() {
    asm volatile("cp.async.wait_group %0;" :: "n"(N) : "memory");
}
__device__ __forceinline__ void ldsm4(uint32_t* r, uint32_t addr) {
    asm volatile("ldmatrix.sync.aligned.m8n8.x4.shared.b16 {%0,%1,%2,%3}, [%4];"
                 : "=r"(r[0]), "=r"(r[1]), "=r"(r[2]), "=r"(r[3]) : "r"(addr));
}
__device__ __forceinline__ void hmma(float* c, const uint32_t* a, uint32_t b0, uint32_t b1) {
    asm volatile("mma.sync.aligned.m16n8k16.row.col.f32.f16.f16.f32 "
                 "{%0,%1,%2,%3}, {%4,%5,%6,%7}, {%8,%9}, {%0,%1,%2,%3};"
                 : "+f"(c[0]), "+f"(c[1]), "+f"(c[2]), "+f"(c[3])
                 : "r"(a[0]), "r"(a[1]), "r"(a[2]), "r"(a[3]), "r"(b0), "r"(b1));
}
__device__ __forceinline__ float tanh_approx(float x) {
    float t;
    asm("tanh.approx.f32 %0, %1;" : "=f"(t) : "f"(x));
    return t;
}
// fast tanh via __expf; |v| clamped (z range << 15)
__device__ __forceinline__ float fast_tanh(float v) {
    float vc = fminf(fmaxf(v, -15.0f), 15.0f);
    float t = __expf(2.0f * vc);
    return __fdividef(t - 1.0f, t + 1.0f);
}

// ---------------- quantization kernel (fp32 -> fp16, x and both W) ----------
__global__ void quant_kernel(const float* __restrict__ x,
                             const float* __restrict__ Wa,
                             const float* __restrict__ Wx) {
    const size_t nx = NELEM / 4;
    const size_t nper = (size_t)DDIM * DDIM / 4;
    size_t i = (size_t)blockIdx.x * blockDim.x + threadIdx.x;
    const float* src;
    __half* dst;
    size_t j;
    if (i < nx)                { src = x;  dst = g_xh; j = i; }
    else if (i < nx + nper)    { src = Wa; dst = g_wh; j = i - nx; }
    else if (i < nx + 2*nper)  { src = Wx; dst = g_wh + (size_t)DDIM*DDIM; j = i - nx - nper; }
    else return;
    float4 v = reinterpret_cast<const float4*>(src)[j];
    float f[4] = {v.x, v.y, v.z, v.w};
    union { __half h[4]; uint2 u; } H;
#pragma unroll
    for (int k = 0; k < 4; k++) H.h[k] = __float2half_rn(f[k]);
    reinterpret_cast<uint2*>(dst)[j] = H.u;
}

// ---------------- GEMM: out[m,e] = act( sum_d x[m,d]*W[e,d] + bias[e] ) ------
// plain fp16, fp32 accumulate. CTA 128x128x64, 256 thr (8 warps, warp tile
// 32x64), 3-stage cp.async ring, TWO CTAs per SM (R12 config — measured best).
// Outputs fp16: ws=0 stores am = 1 - sigmoid(z) = 1/(1+e^z); ws=1 stores tanh.
static constexpr int BK   = 64;              // k elems per chunk (128B of fp16)
static constexpr int ROWB = 144;             // 128B data + 16B pad
static constexpr int XH_TILE_B = 128 * ROWB; // 18432
static constexpr int WH_TILE_B = 128 * ROWB; // 18432
static constexpr int ST_XH = 0;
static constexpr int ST_WH = ST_XH + XH_TILE_B;
static constexpr int STAGE_B = ST_WH + WH_TILE_B;   // 36864
static constexpr int NSTAGE  = 3;
static constexpr int SMEM_GEMM_TOTAL = NSTAGE * STAGE_B;  // 110592 (x2 CTAs)
static constexpr int NKC = DDIM / BK;        // 16

__global__ void __launch_bounds__(256, 2)
gemm_kernel(const float* __restrict__ b_alpha, const float* __restrict__ b_v) {
    extern __shared__ char smem[];
    const uint32_t sbase = smem_u32(smem);
    const int tid = threadIdx.x;
    const int wid = tid >> 5;
    const int l   = tid & 31;
    const int wid_m = wid >> 1;      // 0..3  (32-row slabs)
    const int wid_n = wid & 1;       // 0..1  (64-col slabs)
    const int bn = blockIdx.x;       // 0..7   (N tiles of 128)
    const int bm = blockIdx.y;       // 0..255 (M tiles of 128)
    const int ws = blockIdx.z;       // 0: am/inv-sigmoid, 1: v/tanh

    const __half* __restrict__ Xg  = g_xh + (size_t)bm * 128 * DDIM;
    const __half* __restrict__ Whg = g_wh + (size_t)ws * DDIM * DDIM + (size_t)bn * 128 * DDIM;
    __half* __restrict__ outp = ws ? g_v : g_am;
    const float* __restrict__ bias = ws ? b_v : b_alpha;

    // cp.async mapping: 256 threads; X,W tiles each 128 rows x 128B.
    const int crow  = tid >> 1;      // 0..127
    const int chalf = tid & 1;       // which 64B half of the 128B k-slice
    auto issue_stage = [&](int stage, int kc) {
        const uint32_t s0 = sbase + stage * STAGE_B;
        const size_t gof = (size_t)kc * BK + chalf * 32;  // halves
        const uint32_t so = crow * ROWB + chalf * 64;
#pragma unroll
        for (int j = 0; j < 4; j++)
            cp16(s0 + ST_XH + so + j * 16, Xg + (size_t)crow * DDIM + gof + j * 8);
#pragma unroll
        for (int j = 0; j < 4; j++)
            cp16(s0 + ST_WH + so + j * 16, Whg + (size_t)crow * DDIM + gof + j * 8);
        cp_commit();
    };

    // ldmatrix lane offsets (ROWB=144: 16 rows mod 128 distinct -> conflict-free)
    // B map: n-slice q within an x4 load uses regs {r[2q], r[2q+1]}
    const uint32_t a_lane_off = (uint32_t)((l & 15) * ROWB + (l >> 4) * 16);
    const uint32_t b_lane_off = (uint32_t)(((l & 7) + ((l >> 4) << 3)) * ROWB + ((l >> 3) & 1) * 16);

    float acc[2][8][4];
#pragma unroll
    for (int mi = 0; mi < 2; mi++)
#pragma unroll
        for (int ni = 0; ni < 8; ni++)
#pragma unroll
            for (int r = 0; r < 4; r++) acc[mi][ni][r] = 0.0f;

    issue_stage(0, 0);
    issue_stage(1, 1);

    int rd = 0, wr = 2;
#pragma unroll 1
    for (int kc = 0; kc < NKC; kc++) {
        if (kc + 1 < NKC) cp_wait<1>(); else cp_wait<0>();
        __syncthreads();

        const uint32_t s0 = sbase + rd * STAGE_B;
        const uint32_t sXH = s0 + ST_XH + (uint32_t)(wid_m * 32 * ROWB) + a_lane_off;
        const uint32_t sWH = s0 + ST_WH + (uint32_t)(wid_n * 64 * ROWB) + b_lane_off;

        // prefetch ks=0 A fragments, then overlap cp.async burst issue
        uint32_t ah[2][4];
        ldsm4(ah[0], sXH);
        ldsm4(ah[1], sXH + 16 * ROWB);
        if (kc + 2 < NKC) issue_stage(wr, kc + 2);

#pragma unroll
        for (int ks = 0; ks < 4; ks++) {
#pragma unroll
            for (int p = 0; p < 4; p++) {
                uint32_t bh[4];
                ldsm4(bh, sWH + p * 16 * ROWB + ks * 32);
#pragma unroll
                for (int mi = 0; mi < 2; mi++) {
                    hmma(acc[mi][2*p+0], ah[mi], bh[0], bh[1]);
                    hmma(acc[mi][2*p+1], ah[mi], bh[2], bh[3]);
                }
            }
            if (ks < 3) {
                ldsm4(ah[0], sXH + (ks + 1) * 32);
                ldsm4(ah[1], sXH + 16 * ROWB + (ks + 1) * 32);
            }
        }
        rd = (rd + 1 == NSTAGE) ? 0 : rd + 1;
        wr = (wr + 1 == NSTAGE) ? 0 : wr + 1;
    }

    // epilogue: z = acc + bias; activation; __half2 stores
    const int row_base = bm * 128 + wid_m * 32 + (l >> 2);
    const int col_base = bn * 128 + wid_n * 64 + (l & 3) * 2;
#pragma unroll
    for (int mi = 0; mi < 2; mi++) {
#pragma unroll
        for (int n8 = 0; n8 < 8; n8++) {
            const int col = col_base + n8 * 8;
            const float bia0 = __ldg(&bias[col]);
            const float bia1 = __ldg(&bias[col + 1]);
#pragma unroll
            for (int half = 0; half < 2; half++) {
                const int row = row_base + mi * 16 + half * 8;
                float v0 = acc[mi][n8][half*2+0] + bia0;
                float v1 = acc[mi][n8][half*2+1] + bia1;
                float o0, o1;
                if (ws) { o0 = fast_tanh(v0); o1 = fast_tanh(v1); }
                else {   // am = 1 - sigmoid(z) = 1/(1+e^{+z})
                    o0 = __fdividef(1.0f, 1.0f + __expf(v0));
                    o1 = __fdividef(1.0f, 1.0f + __expf(v1));
                }
                *reinterpret_cast<__half2*>(outp + (size_t)row * DDIM + col) =
                    __floats2half2_rn(o0, o1);
            }
        }
    }
}

// ---------------- scan kernel: 16384 independent recurrences over T ----------
// 32-thr blocks; 4-slot cp.async half ring. In-chain gate via MUFU.TANH.
// a = 1 - am (am stored inverted so fp16 error stays bounded under 1/(1-a)
// amplification). Off-chain silu keeps exact __expf sigmoid.
__global__ void __launch_bounds__(32)
scan_kernel(const float* __restrict__ d_g, const float* __restrict__ b_g,
            float* __restrict__ out) {
    __shared__ __align__(16) __half sA[4][8][32];
    __shared__ __align__(16) __half sV[4][8][32];
    const int lane = threadIdx.x;
    const int base = blockIdx.x * 32;
    const int idx = base + lane;
    const int d = idx & (DDIM - 1);
    const float dq = -0.5f * __ldg(&d_g[d]);   // tanh arg: dq*|h| + bq
    const float bq =  0.5f * __ldg(&b_g[d]);

    float* houtp = out + (size_t)TT * SBD;   // h buffer [T+1, B, D]
    houtp[idx] = 0.0f;                       // h0

    const __half* A = g_am;
    const __half* V = g_v;

    // chunk = 8 steps; per chunk: A 8x32 half (64B/step = 4x16B) + V same
    // = 64 segs of 16B; 32 threads x 2 segs each.
    auto issue_chunk = [&](int c) {
        const int slot = c & 3;
#pragma unroll
        for (int u = 0; u < 2; u++) {
            const int s = lane + u * 32;           // 0..63
            const int s2 = s & 31;
            const int step = s2 >> 2, sg = s2 & 3;
            const size_t goff = (size_t)(c * 8 + step) * SBD + base + sg * 8;
            if (s < 32) cp16(smem_u32(&sA[slot][step][sg * 8]), A + goff);
            else        cp16(smem_u32(&sV[slot][step][sg * 8]), V + goff);
        }
        cp_commit();
    };

    issue_chunk(0);
    issue_chunk(1);
    issue_chunk(2);

    float h = 0.0f;
#pragma unroll 1
    for (int t0 = 0; t0 < TT; t0 += 8) {
        __syncwarp();
        if (t0 + 24 < TT)       { issue_chunk((t0 >> 3) + 3); cp_wait<3>(); }
        else if (t0 + 24 == TT) cp_wait<2>();
        else if (t0 + 16 == TT) cp_wait<1>();
        else                    cp_wait<0>();
        __syncwarp();

        const int slot = (t0 >> 3) & 3;
#pragma unroll
        for (int i = 0; i < 8; i++) {
            const float am = __half2float(sA[slot][i][lane]);
            const float v  = __half2float(sV[slot][i][lane]);
            const float halfc = 0.5f * am * v;            // off chain
            const float a = 1.0f - am;                    // off chain
            const float base_h = fmaf(a, h, halfc);       // parallel w/ fabs path
            const float u = fmaf(dq, fabsf(h), bq);       // chain: fabs->fma
            const float t = tanh_approx(u);               // chain: MUFU.TANH
            h = fmaf(halfc, t, base_h);                   // chain: fma -> h_new
            const float sg = __fdividef(1.0f, 1.0f + __expf(-h));  // off chain
            const size_t tt = (size_t)(t0 + i);
            out[tt * SBD + idx] = h * h * sg;             // h * silu(h)
            houtp[(tt + 1) * SBD + idx] = h;
        }
    }
}

// ---------------- launcher ----------------
extern "C" void kernel_launch(void* const* d_in, const int* in_sizes, int n_in,
                              void* d_out, int out_size) {
    const float* x       = (const float*)d_in[0];
    const float* W_alpha = (const float*)d_in[1];
    const float* b_alpha = (const float*)d_in[2];
    const float* d_g     = (const float*)d_in[3];
    const float* b_g     = (const float*)d_in[4];
    const float* W_x     = (const float*)d_in[5];
    const float* b_v     = (const float*)d_in[6];
    float* out = (float*)d_out;

    (void)in_sizes; (void)n_in; (void)out_size;

    cudaFuncSetAttribute(gemm_kernel, cudaFuncAttributeMaxDynamicSharedMemorySize,
                         SMEM_GEMM_TOTAL);

    // 1) quantize fp32 -> fp16 (x + both W in one launch)
    {
        const size_t tot = NELEM / 4 + 2 * ((size_t)DDIM * DDIM / 4);
        quant_kernel<<<(int)((tot + 255) / 256), 256>>>(x, W_alpha, W_x);
    }

    // 2) single fused GEMM launch (z=0: am/inv-sigmoid, z=1: v/tanh)
    {
        dim3 grid(DDIM / 128, MM / 128, 2);
        gemm_kernel<<<grid, 256, SMEM_GEMM_TOTAL>>>(b_alpha, b_v);
    }

    // 3) sequential scan, fully parallel over B*D lanes
    scan_kernel<<<SBD / 32, 32>>>(d_g, b_g, out);
}

// round 17
// speedup vs baseline: 1.2654x; 1.0155x over previous
#include <cuda_runtime.h>
#include <cuda_fp16.h>
#include <cstdint>

// ---------------- problem dims ----------------
#define TT 2048
#define BB 16
#define DDIM 1024
#define MM (TT*BB)            // 32768 rows
#define SBD (BB*DDIM)         // 16384 lanes in scan
#define NELEM ((size_t)MM*DDIM)

// ---------------- device scratch (no cudaMalloc allowed) ----------------
__device__ __half g_xh[NELEM];
__device__ __half g_wh[2*DDIM*DDIM];
__device__ __half g_am[NELEM];    // 1 - alpha  (fp16, inverted storage)
__device__ __half g_v[NELEM];     // tanh(zv)   (fp16)

// ---------------- PTX helpers (base sm_103 target: no tcgen05/TMA) ---------
__device__ __forceinline__ uint32_t smem_u32(const void* p) {
    uint32_t a;
    asm("{ .reg .u64 t; cvta.to.shared.u64 t, %1; cvt.u32.u64 %0, t; }" : "=r"(a) : "l"(p));
    return a;
}
__device__ __forceinline__ void cp16(uint32_t s, const void* g) {
    asm volatile("cp.async.cg.shared.global [%0], [%1], 16;" :: "r"(s), "l"(g));
}
__device__ __forceinline__ void cp_commit() {
    asm volatile("cp.async.commit_group;" ::: "memory");
}
template <int N>
__device__ __forceinline__ void cp_wait() {
    asm volatile("cp.async.wait_group %0;" :: "n"(N) : "memory");
}
__device__ __forceinline__ void ldsm4(uint32_t* r, uint32_t addr) {
    asm volatile("ldmatrix.sync.aligned.m8n8.x4.shared.b16 {%0,%1,%2,%3}, [%4];"
                 : "=r"(r[0]), "=r"(r[1]), "=r"(r[2]), "=r"(r[3]) : "r"(addr));
}
__device__ __forceinline__ void hmma(float* c, const uint32_t* a, uint32_t b0, uint32_t b1) {
    asm volatile("mma.sync.aligned.m16n8k16.row.col.f32.f16.f16.f32 "
                 "{%0,%1,%2,%3}, {%4,%5,%6,%7}, {%8,%9}, {%0,%1,%2,%3};"
                 : "+f"(c[0]), "+f"(c[1]), "+f"(c[2]), "+f"(c[3])
                 : "r"(a[0]), "r"(a[1]), "r"(a[2]), "r"(a[3]), "r"(b0), "r"(b1));
}
__device__ __forceinline__ float tanh_approx(float x) {
    float t;
    asm("tanh.approx.f32 %0, %1;" : "=f"(t) : "f"(x));
    return t;
}
// fast tanh via __expf; |v| clamped (z range << 15)
__device__ __forceinline__ float fast_tanh(float v) {
    float vc = fminf(fmaxf(v, -15.0f), 15.0f);
    float t = __expf(2.0f * vc);
    return __fdividef(t - 1.0f, t + 1.0f);
}

// ---------------- quantization kernel (fp32 -> fp16, x and both W) ----------
__global__ void quant_kernel(const float* __restrict__ x,
                             const float* __restrict__ Wa,
                             const float* __restrict__ Wx) {
    const size_t nx = NELEM / 4;
    const size_t nper = (size_t)DDIM * DDIM / 4;
    size_t i = (size_t)blockIdx.x * blockDim.x + threadIdx.x;
    const float* src;
    __half* dst;
    size_t j;
    if (i < nx)                { src = x;  dst = g_xh; j = i; }
    else if (i < nx + nper)    { src = Wa; dst = g_wh; j = i - nx; }
    else if (i < nx + 2*nper)  { src = Wx; dst = g_wh + (size_t)DDIM*DDIM; j = i - nx - nper; }
    else return;
    float4 v = reinterpret_cast<const float4*>(src)[j];
    float f[4] = {v.x, v.y, v.z, v.w};
    union { __half h[4]; uint2 u; } H;
#pragma unroll
    for (int k = 0; k < 4; k++) H.h[k] = __float2half_rn(f[k]);
    reinterpret_cast<uint2*>(dst)[j] = H.u;
}

// ---------------- GEMM: out[m,e] = act( sum_d x[m,d]*W[e,d] + bias[e] ) ------
// plain fp16, fp32 accumulate. CTA 128x128x64, 256 thr (8 warps, warp tile
// 32x64), 3-stage cp.async ring, TWO CTAs per SM (measured-best config).
// Outputs fp16: ws=0 stores am = 1 - sigmoid(z) = 1/(1+e^z); ws=1 stores tanh.
static constexpr int BK   = 64;              // k elems per chunk (128B of fp16)
static constexpr int ROWB = 144;             // 128B data + 16B pad
static constexpr int XH_TILE_B = 128 * ROWB; // 18432
static constexpr int WH_TILE_B = 128 * ROWB; // 18432
static constexpr int ST_XH = 0;
static constexpr int ST_WH = ST_XH + XH_TILE_B;
static constexpr int STAGE_B = ST_WH + WH_TILE_B;   // 36864
static constexpr int NSTAGE  = 3;
static constexpr int SMEM_GEMM_TOTAL = NSTAGE * STAGE_B;  // 110592 (x2 CTAs)
static constexpr int NKC = DDIM / BK;        // 16

__global__ void __launch_bounds__(256, 2)
gemm_kernel(const float* __restrict__ b_alpha, const float* __restrict__ b_v) {
    extern __shared__ char smem[];
    const uint32_t sbase = smem_u32(smem);
    const int tid = threadIdx.x;
    const int wid = tid >> 5;
    const int l   = tid & 31;
    const int wid_m = wid >> 1;      // 0..3  (32-row slabs)
    const int wid_n = wid & 1;       // 0..1  (64-col slabs)
    const int bn = blockIdx.x;       // 0..7   (N tiles of 128)
    const int bm = blockIdx.y;       // 0..255 (M tiles of 128)
    const int ws = blockIdx.z;       // 0: am/inv-sigmoid, 1: v/tanh

    const __half* __restrict__ Xg  = g_xh + (size_t)bm * 128 * DDIM;
    const __half* __restrict__ Whg = g_wh + (size_t)ws * DDIM * DDIM + (size_t)bn * 128 * DDIM;
    __half* __restrict__ outp = ws ? g_v : g_am;
    const float* __restrict__ bias = ws ? b_v : b_alpha;

    // cp.async mapping: 256 threads; X,W tiles each 128 rows x 128B.
    const int crow  = tid >> 1;      // 0..127
    const int chalf = tid & 1;       // which 64B half of the 128B k-slice
    auto issue_stage = [&](int stage, int kc) {
        const uint32_t s0 = sbase + stage * STAGE_B;
        const size_t gof = (size_t)kc * BK + chalf * 32;  // halves
        const uint32_t so = crow * ROWB + chalf * 64;
#pragma unroll
        for (int j = 0; j < 4; j++)
            cp16(s0 + ST_XH + so + j * 16, Xg + (size_t)crow * DDIM + gof + j * 8);
#pragma unroll
        for (int j = 0; j < 4; j++)
            cp16(s0 + ST_WH + so + j * 16, Whg + (size_t)crow * DDIM + gof + j * 8);
        cp_commit();
    };

    // ldmatrix lane offsets (ROWB=144: 16 rows mod 128 distinct -> conflict-free)
    // B map: n-slice q within an x4 load uses regs {r[2q], r[2q+1]}
    const uint32_t a_lane_off = (uint32_t)((l & 15) * ROWB + (l >> 4) * 16);
    const uint32_t b_lane_off = (uint32_t)(((l & 7) + ((l >> 4) << 3)) * ROWB + ((l >> 3) & 1) * 16);

    float acc[2][8][4];
#pragma unroll
    for (int mi = 0; mi < 2; mi++)
#pragma unroll
        for (int ni = 0; ni < 8; ni++)
#pragma unroll
            for (int r = 0; r < 4; r++) acc[mi][ni][r] = 0.0f;

    issue_stage(0, 0);
    issue_stage(1, 1);

    int rd = 0, wr = 2;
#pragma unroll 1
    for (int kc = 0; kc < NKC; kc++) {
        if (kc + 1 < NKC) cp_wait<1>(); else cp_wait<0>();
        __syncthreads();

        const uint32_t s0 = sbase + rd * STAGE_B;
        const uint32_t sXH = s0 + ST_XH + (uint32_t)(wid_m * 32 * ROWB) + a_lane_off;
        const uint32_t sWH = s0 + ST_WH + (uint32_t)(wid_n * 64 * ROWB) + b_lane_off;

        // prefetch ks=0 A fragments, then overlap cp.async burst issue
        uint32_t ah[2][4];
        ldsm4(ah[0], sXH);
        ldsm4(ah[1], sXH + 16 * ROWB);
        if (kc + 2 < NKC) issue_stage(wr, kc + 2);

#pragma unroll
        for (int ks = 0; ks < 4; ks++) {
#pragma unroll
            for (int p = 0; p < 4; p++) {
                uint32_t bh[4];
                ldsm4(bh, sWH + p * 16 * ROWB + ks * 32);
#pragma unroll
                for (int mi = 0; mi < 2; mi++) {
                    hmma(acc[mi][2*p+0], ah[mi], bh[0], bh[1]);
                    hmma(acc[mi][2*p+1], ah[mi], bh[2], bh[3]);
                }
            }
            if (ks < 3) {
                ldsm4(ah[0], sXH + (ks + 1) * 32);
                ldsm4(ah[1], sXH + 16 * ROWB + (ks + 1) * 32);
            }
        }
        rd = (rd + 1 == NSTAGE) ? 0 : rd + 1;
        wr = (wr + 1 == NSTAGE) ? 0 : wr + 1;
    }

    // epilogue: z = acc + bias; activation; __half2 stores
    const int row_base = bm * 128 + wid_m * 32 + (l >> 2);
    const int col_base = bn * 128 + wid_n * 64 + (l & 3) * 2;
#pragma unroll
    for (int mi = 0; mi < 2; mi++) {
#pragma unroll
        for (int n8 = 0; n8 < 8; n8++) {
            const int col = col_base + n8 * 8;
            const float bia0 = __ldg(&bias[col]);
            const float bia1 = __ldg(&bias[col + 1]);
#pragma unroll
            for (int half = 0; half < 2; half++) {
                const int row = row_base + mi * 16 + half * 8;
                float v0 = acc[mi][n8][half*2+0] + bia0;
                float v1 = acc[mi][n8][half*2+1] + bia1;
                float o0, o1;
                if (ws) { o0 = fast_tanh(v0); o1 = fast_tanh(v1); }
                else {   // am = 1 - sigmoid(z) = 1/(1+e^{+z})
                    o0 = __fdividef(1.0f, 1.0f + __expf(v0));
                    o1 = __fdividef(1.0f, 1.0f + __expf(v1));
                }
                *reinterpret_cast<__half2*>(outp + (size_t)row * DDIM + col) =
                    __floats2half2_rn(o0, o1);
            }
        }
    }
}

// ---------------- scan kernel: 16384 independent recurrences over T ----------
// 32-thr blocks; 8-slot cp.async half ring with 6-chunk (48-step) load lead
// for deeper MLP on the DRAM stream. In-chain gate via MUFU.TANH. a = 1 - am
// (am stored inverted so fp16 error stays bounded under 1/(1-a) amplification).
// Off-chain silu keeps exact __expf sigmoid.
static constexpr int SC_SLOTS = 8;
static constexpr int SC_LEAD  = 6;     // chunks issued ahead of consumption
static constexpr int SC_NCH   = TT / 8;   // 256 chunks

__global__ void __launch_bounds__(32)
scan_kernel(const float* __restrict__ d_g, const float* __restrict__ b_g,
            float* __restrict__ out) {
    __shared__ __align__(16) __half sA[SC_SLOTS][8][32];
    __shared__ __align__(16) __half sV[SC_SLOTS][8][32];
    const int lane = threadIdx.x;
    const int base = blockIdx.x * 32;
    const int idx = base + lane;
    const int d = idx & (DDIM - 1);
    const float dq = -0.5f * __ldg(&d_g[d]);   // tanh arg: dq*|h| + bq
    const float bq =  0.5f * __ldg(&b_g[d]);

    float* houtp = out + (size_t)TT * SBD;   // h buffer [T+1, B, D]
    houtp[idx] = 0.0f;                       // h0

    const __half* A = g_am;
    const __half* V = g_v;

    // chunk = 8 steps; per chunk: A 8x32 half (64B/step = 4x16B) + V same
    // = 64 segs of 16B; 32 threads x 2 segs each.
    auto issue_chunk = [&](int c) {
        const int slot = c & (SC_SLOTS - 1);
#pragma unroll
        for (int u = 0; u < 2; u++) {
            const int s = lane + u * 32;           // 0..63
            const int s2 = s & 31;
            const int step = s2 >> 2, sg = s2 & 3;
            const size_t goff = (size_t)(c * 8 + step) * SBD + base + sg * 8;
            if (s < 32) cp16(smem_u32(&sA[slot][step][sg * 8]), A + goff);
            else        cp16(smem_u32(&sV[slot][step][sg * 8]), V + goff);
        }
        cp_commit();
    };

#pragma unroll
    for (int c = 0; c < SC_LEAD; c++) issue_chunk(c);

    float h = 0.0f;
#pragma unroll 1
    for (int t0 = 0; t0 < TT; t0 += 8) {
        const int c = t0 >> 3;
        __syncwarp();
        if (c + SC_LEAD < SC_NCH) { issue_chunk(c + SC_LEAD); cp_wait<SC_LEAD>(); }
        else if (c == SC_NCH - 6) cp_wait<5>();
        else if (c == SC_NCH - 5) cp_wait<4>();
        else if (c == SC_NCH - 4) cp_wait<3>();
        else if (c == SC_NCH - 3) cp_wait<2>();
        else if (c == SC_NCH - 2) cp_wait<1>();
        else                      cp_wait<0>();
        __syncwarp();

        const int slot = c & (SC_SLOTS - 1);
#pragma unroll
        for (int i = 0; i < 8; i++) {
            const float am = __half2float(sA[slot][i][lane]);
            const float v  = __half2float(sV[slot][i][lane]);
            const float halfc = 0.5f * am * v;            // off chain
            const float a = 1.0f - am;                    // off chain
            const float base_h = fmaf(a, h, halfc);       // parallel w/ fabs path
            const float u = fmaf(dq, fabsf(h), bq);       // chain: fabs->fma
            const float t = tanh_approx(u);               // chain: MUFU.TANH
            h = fmaf(halfc, t, base_h);                   // chain: fma -> h_new
            const float sg = __fdividef(1.0f, 1.0f + __expf(-h));  // off chain
            const size_t tt = (size_t)(t0 + i);
            out[tt * SBD + idx] = h * h * sg;             // h * silu(h)
            houtp[(tt + 1) * SBD + idx] = h;
        }
    }
}

// ---------------- launcher ----------------
extern "C" void kernel_launch(void* const* d_in, const int* in_sizes, int n_in,
                              void* d_out, int out_size) {
    const float* x       = (const float*)d_in[0];
    const float* W_alpha = (const float*)d_in[1];
    const float* b_alpha = (const float*)d_in[2];
    const float* d_g     = (const float*)d_in[3];
    const float* b_g     = (const float*)d_in[4];
    const float* W_x     = (const float*)d_in[5];
    const float* b_v     = (const float*)d_in[6];
    float* out = (float*)d_out;

    (void)in_sizes; (void)n_in; (void)out_size;

    cudaFuncSetAttribute(gemm_kernel, cudaFuncAttributeMaxDynamicSharedMemorySize,
                         SMEM_GEMM_TOTAL);

    // 1) quantize fp32 -> fp16 (x + both W in one launch)
    {
        const size_t tot = NELEM / 4 + 2 * ((size_t)DDIM * DDIM / 4);
        quant_kernel<<<(int)((tot + 255) / 256), 256>>>(x, W_alpha, W_x);
    }

    // 2) single fused GEMM launch (z=0: am/inv-sigmoid, z=1: v/tanh)
    {
        dim3 grid(DDIM / 128, MM / 128, 2);
        gemm_kernel<<<grid, 256, SMEM_GEMM_TOTAL>>>(b_alpha, b_v);
    }

    // 3) sequential scan, fully parallel over B*D lanes
    scan_kernel<<<SBD / 32, 32>>>(d_g, b_g, out);
}